// round 15
// baseline (speedup 1.0000x reference)
#include <cuda_runtime.h>
#include <cuda_fp16.h>

#define NBLK 128
#define NTHR 512
#define T_STEPS 512
#define PLEN 64

#define BK 128                // k-halves per stage
#define RING 4
#define LA 3
#define SA 136                // smem row stride in halves (BK + 8)
#define ASTAGE (64 * SA)      // halves
#define BSTAGE (32 * SA)      // halves
#define NKS 8                 // k-split warps
#define GATES_OFF (RING * (ASTAGE + BSTAGE))            // halves
#define WFC_OFF   (GATES_OFF + NKS * 64 * 33 * 2)       // gates: 8 bufs of 64x33 floats
#define SMEM_BYTES ((WFC_OFF + 8 * 1024) * 2)

#define S0 9                  // layer0: 8 H-stages + 1 X-stage (K=1152)
#define S12 16                // layers 1/2: 8 H + 8 X (K=2048)
#define L0SZ (128 * S0 * 4096)
#define L12SZ (128 * S12 * 4096)

// ---------------- device state ----------------
__device__ __half g_Wp0[L0SZ];
__device__ __half g_Wp1[L12SZ];
__device__ __half g_Wp2[L12SZ];
__device__ __half g_Wfch[128 * 1024];
__device__ float  g_bsum[3 * 4096];
__device__ __half g_In0[64 * 128];
__device__ __half g_X1[64 * 1024];
__device__ __half g_X2[64 * 1024];
__device__ __half g_Xfc[64 * 1024];
__device__ __half g_Hst[3][2][64 * 1024];
__device__ float  g_Cst[3 * 64 * 1024];
__device__ unsigned g_ck[3 * 16 * 32];   // per-layer per-chunk counters (128B stride; 8 used/layer)
__device__ unsigned g_fin;               // In0 production counter (128/step)

// ---------------- helpers ----------------
__device__ __forceinline__ float sigf(float v) { return 1.0f / (1.0f + expf(-v)); }

__device__ __forceinline__ unsigned smaddr(const void* p) {
    return (unsigned)__cvta_generic_to_shared(p);
}
__device__ __forceinline__ void cp16(unsigned dst, const void* src) {
    asm volatile("cp.async.cg.shared.global [%0], [%1], 16;" :: "r"(dst), "l"(src));
}
__device__ __forceinline__ void cp_commit() { asm volatile("cp.async.commit_group;"); }

__device__ __forceinline__ void ldsm4(unsigned& r0, unsigned& r1, unsigned& r2, unsigned& r3,
                                      unsigned addr) {
    asm volatile("ldmatrix.sync.aligned.m8n8.x4.shared.b16 {%0,%1,%2,%3}, [%4];"
                 : "=r"(r0), "=r"(r1), "=r"(r2), "=r"(r3) : "r"(addr));
}
__device__ __forceinline__ void mma16816(float c[4],
    unsigned a0, unsigned a1, unsigned a2, unsigned a3, unsigned b0, unsigned b1) {
    asm volatile("mma.sync.aligned.m16n8k16.row.col.f32.f16.f16.f32 "
        "{%0,%1,%2,%3}, {%4,%5,%6,%7}, {%8,%9}, {%0,%1,%2,%3};"
        : "+f"(c[0]), "+f"(c[1]), "+f"(c[2]), "+f"(c[3])
        : "r"(a0), "r"(a1), "r"(a2), "r"(a3), "r"(b0), "r"(b1));
}

__device__ __forceinline__ void poll_ge(const unsigned* a, unsigned target) {
    unsigned cur;
    do {
        asm volatile("ld.acquire.gpu.global.u32 %0, [%1];" : "=r"(cur) : "l"(a));
    } while ((int)(cur - target) < 0);
}
__device__ __forceinline__ void release_add(unsigned* a) {
    asm volatile("red.release.gpu.global.add.u32 [%0], %1;" :: "l"(a), "r"(1u));
}

// ---------------- packing / init ----------------
// Wp[((bc*S + s)*32 + col)*128 + kk]; col = gate*8 + nl; H-part first
// (s<8 -> Whh k=s*128+kk; s>=8 -> Wih); row = gate*1024 + bc*8 + nl.
__global__ void pack_all(const float* __restrict__ Wih0, const float* __restrict__ Whh0,
                         const float* __restrict__ Wih1, const float* __restrict__ Whh1,
                         const float* __restrict__ Wih2, const float* __restrict__ Whh2) {
    int idx = blockIdx.x * blockDim.x + threadIdx.x;
    const float *Wih, *Whh;
    __half* Wp;
    int S, Kin, i = idx;
    if (i < L0SZ)               { Wp = g_Wp0; S = S0;  Kin = 128;  Wih = Wih0; Whh = Whh0; }
    else if (i < L0SZ + L12SZ)  { i -= L0SZ;  Wp = g_Wp1; S = S12; Kin = 1024; Wih = Wih1; Whh = Whh1; }
    else if (i < L0SZ + 2*L12SZ){ i -= L0SZ + L12SZ; Wp = g_Wp2; S = S12; Kin = 1024; Wih = Wih2; Whh = Whh2; }
    else return;
    int kk   = i & 127;
    int col  = (i >> 7) & 31;
    int rest = i >> 12;
    int s    = rest % S;
    int bc   = rest / S;
    int row  = ((col >> 3) << 10) + bc * 8 + (col & 7);
    float v  = (s < 8) ? Whh[row * 1024 + s * 128 + kk]
                       : Wih[row * Kin + (s - 8) * 128 + kk];
    Wp[i] = __float2half(v);
}

__global__ void pack_fc(const float* __restrict__ Wfc) {
    int i = blockIdx.x * blockDim.x + threadIdx.x;
    if (i < 128 * 1024) g_Wfch[i] = __float2half(Wfc[i]);
}

__global__ void init_state(const float* __restrict__ x, const float* __restrict__ h0,
                           const float* __restrict__ c0,
                           const float* __restrict__ bih0, const float* __restrict__ bhh0,
                           const float* __restrict__ bih1, const float* __restrict__ bhh1,
                           const float* __restrict__ bih2, const float* __restrict__ bhh2,
                           float* __restrict__ out) {
    int i = blockIdx.x * blockDim.x + threadIdx.x;
    if (i == 0) g_fin = 0;
    if (i < 3 * 16 * 32) g_ck[i] = 0;
    if (i < 8192) { float v = x[i]; g_In0[i] = __float2half(v); out[i] = v; }
    if (i < 3 * 65536) {
        g_Hst[i >> 16][0][i & 65535] = __float2half(h0[i]);
        g_Cst[i] = c0[i];
    }
    if (i < 4096) {
        g_bsum[i]        = bih0[i] + bhh0[i];
        g_bsum[4096 + i] = bih1[i] + bhh1[i];
        g_bsum[8192 + i] = bih2[i] + bhh2[i];
    }
}

// ---------------- main persistent kernel ----------------
extern __shared__ __half sm_raw[];

struct Ctx {
    int tid, bc;
    int ar0, au0, ar1, bcol, bu;       // cp.async indices
    unsigned AsBase, BsBase;
    unsigned aOff, bOff;               // per-lane ldmatrix offsets (bytes)
    int mh, ks;                        // warp mapping: m-half (32 rows), k-split (16 halves)
};

__device__ __forceinline__ void load_stage(const Ctx& cx,
    const __half* __restrict__ Hp, const __half* __restrict__ Xin, int ldX,
    const __half* __restrict__ wseg, int s, int slot)
{
    unsigned adst = cx.AsBase + (unsigned)(slot * ASTAGE) * 2u;
    unsigned bdst = cx.BsBase + (unsigned)(slot * BSTAGE) * 2u;
    const __half* a; int ld;
    if (s < 8) { a = Hp + s * BK; ld = 1024; }
    else       { a = Xin + (s - 8) * BK; ld = ldX; }
    cp16(adst + (unsigned)(cx.ar0 * SA + cx.au0 * 8) * 2u, a + cx.ar0 * ld + cx.au0 * 8);
    cp16(adst + (unsigned)(cx.ar1 * SA + cx.au0 * 8) * 2u, a + cx.ar1 * ld + cx.au0 * 8);
    cp16(bdst + (unsigned)(cx.bcol * SA + cx.bu * 8) * 2u,
         wseg + (size_t)s * 4096 + cx.bcol * 128 + cx.bu * 8);
}

// layer GEMM + fused LSTM cell; X-stage loads gated by per-chunk dataflow counters
__device__ __forceinline__ void gemm_epi(const Ctx& cx, int stages, int l, int t,
    const __half* __restrict__ Hp, const __half* __restrict__ Xin, int ldX,
    const __half* __restrict__ wseg,
    const float* __restrict__ bsumL, float* __restrict__ Cl,
    __half* __restrict__ Hnext, __half* __restrict__ Xnext)
{
    float* gates = (float*)(sm_raw + GATES_OFF);    // 8 bufs of 64x33 floats

    float acc[2][2][2][4];
#pragma unroll
    for (int a = 0; a < 2; ++a)
#pragma unroll
        for (int b = 0; b < 2; ++b)
#pragma unroll
            for (int c = 0; c < 2; ++c)
#pragma unroll
                for (int d = 0; d < 4; ++d) acc[a][b][c][d] = 0.f;

    // prologue: first LA stages are H-part (proven ready by transitive acquire chain)
#pragma unroll
    for (int s = 0; s < LA; ++s) {
        load_stage(cx, Hp, Xin, ldX, wseg, s, s);
        cp_commit();
    }

#pragma unroll 1
    for (int s = 0; s < stages; ++s) {
        asm volatile("cp.async.wait_group %0;" :: "n"(LA - 1));
        __syncthreads();
        int u = s + LA;
        if (u < stages) {
            if (u >= 8) {                               // X-stage: wait for producer chunk
                if (cx.tid == 0) {
                    if (l == 0) poll_ge(&g_fin, 128u * (unsigned)t);
                    else        poll_ge(g_ck + (((l - 1) * 16 + (u - 8)) << 5),
                                        16u * (unsigned)(t + 1));
                }
                __syncthreads();
            }
            load_stage(cx, Hp, Xin, ldX, wseg, u, u & (RING - 1));
        }
        cp_commit();

        int slot = s & (RING - 1);
        unsigned aBase = cx.AsBase + (unsigned)(slot * ASTAGE) * 2u + cx.aOff;
        unsigned bBase = cx.BsBase + (unsigned)(slot * BSTAGE) * 2u + cx.bOff;
        unsigned b0[4], b1[4];
        ldsm4(b0[0], b0[1], b0[2], b0[3], bBase);
        ldsm4(b1[0], b1[1], b1[2], b1[3], bBase + 16u * SA * 2u);
#pragma unroll
        for (int mt = 0; mt < 2; ++mt) {
            unsigned a0, a1, a2, a3;
            ldsm4(a0, a1, a2, a3, aBase + mt * (16u * SA * 2u));
            mma16816(acc[mt][0][0], a0, a1, a2, a3, b0[0], b0[1]);
            mma16816(acc[mt][0][1], a0, a1, a2, a3, b0[2], b0[3]);
            mma16816(acc[mt][1][0], a0, a1, a2, a3, b1[0], b1[1]);
            mma16816(acc[mt][1][1], a0, a1, a2, a3, b1[2], b1[3]);
        }
    }

    // store partial gates (per k-split buffer)
    {
        const int lane = cx.tid & 31;
        float* gk = gates + cx.ks * (64 * 33);
        int r = lane >> 2, p2 = (lane & 3) * 2;
#pragma unroll
        for (int mt = 0; mt < 2; ++mt)
#pragma unroll
            for (int hb = 0; hb < 2; ++hb)
#pragma unroll
                for (int n8 = 0; n8 < 2; ++n8) {
                    int row = cx.mh * 32 + mt * 16 + r;
                    int col = hb * 16 + n8 * 8 + p2;
                    float* q = acc[mt][hb][n8];
                    gk[row * 33 + col]           = q[0];
                    gk[row * 33 + col + 1]       = q[1];
                    gk[(row + 8) * 33 + col]     = q[2];
                    gk[(row + 8) * 33 + col + 1] = q[3];
                }
    }
    __syncthreads();

    // fused LSTM cell epilogue: 512 threads, one (batch, hid) each
    {
        int b = cx.tid >> 3, nl = cx.tid & 7;
        int ng = cx.bc * 8 + nl;
        int e = b * 33 + nl;
        float gi = 0.f, gf = 0.f, gg = 0.f, go = 0.f;
#pragma unroll
        for (int k = 0; k < NKS; ++k) {
            const float* g = gates + k * (64 * 33);
            gi += g[e];
            gf += g[e + 8];
            gg += g[e + 16];
            go += g[e + 24];
        }
        gi += bsumL[ng]; gf += bsumL[1024 + ng];
        gg += bsumL[2048 + ng]; go += bsumL[3072 + ng];
        float c  = Cl[b * 1024 + ng];
        float cn = sigf(gf) * c + sigf(gi) * tanhf(gg);
        float h  = sigf(go) * tanhf(cn);
        Cl[b * 1024 + ng] = cn;
        __half hh = __float2half(h);
        Hnext[b * 1024 + ng] = hh;
        Xnext[b * 1024 + ng] = hh;
    }
    __threadfence();
    __syncthreads();
    if (cx.tid == 0)
        release_add(g_ck + ((l * 16 + (cx.bc >> 4)) << 5));   // publish our 8 columns
}

__global__ void __launch_bounds__(NTHR, 1)
lstm_main(const float* __restrict__ x, const float* __restrict__ bfc,
          float* __restrict__ out)
{
    const int tid = threadIdx.x, bc = blockIdx.x;
    Ctx cx;
    cx.tid = tid; cx.bc = bc;
    cx.ar0 = tid >> 4;          cx.au0 = tid & 15;
    cx.ar1 = (tid + 512) >> 4;
    cx.bcol = tid >> 4;         cx.bu = tid & 15;
    cx.AsBase = smaddr(sm_raw);
    cx.BsBase = smaddr(sm_raw + RING * ASTAGE);
    {
        const int lane = tid & 31, wid = tid >> 5;
        cx.mh = wid & 1;                       // m-half (32 rows)
        cx.ks = wid >> 1;                      // k-chunk 0..7 (16 halves each)
        int aRow = cx.mh * 32 + ((lane >> 3) & 1) * 8 + (lane & 7);
        cx.aOff = (unsigned)(aRow * SA + (lane >> 4) * 8 + cx.ks * 16) * 2u;
        int bRow = ((lane >> 4) & 1) * 8 + (lane & 7);
        cx.bOff = (unsigned)(bRow * SA + ((lane >> 3) & 1) * 8 + cx.ks * 16) * 2u;
    }
    __half* sWfc = sm_raw + WFC_OFF;

    // cache this CTA's fc weight slice in smem (8 rows x 1024 halves)
    {
        const int cg = bc & 15;
        const __half* src = g_Wfch + cg * 8 * 1024;
#pragma unroll
        for (int i = 0; i < 2; ++i) {
            int e = (tid + i * 512) * 8;
            cp16(smaddr(sWfc + e), src + e);
        }
        cp_commit();
        asm volatile("cp.async.wait_group 0;");
        __syncthreads();
    }

    const __half* Wb0 = g_Wp0 + (size_t)bc * S0 * 4096;
    const __half* Wb1 = g_Wp1 + (size_t)bc * S12 * 4096;
    const __half* Wb2 = g_Wp2 + (size_t)bc * S12 * 4096;

#pragma unroll 1
    for (int t = 0; t < T_STEPS - 1; ++t) {
        int p = t & 1;

        gemm_epi(cx, S0, 0, t, g_Hst[0][p], g_In0, 128, Wb0,
                 g_bsum, g_Cst, g_Hst[0][p ^ 1], g_X1);
        gemm_epi(cx, S12, 1, t, g_Hst[1][p], g_X1, 1024, Wb1,
                 g_bsum + 4096, g_Cst + 65536, g_Hst[1][p ^ 1], g_X2);
        gemm_epi(cx, S12, 2, t, g_Hst[2][p], g_X2, 1024, Wb2,
                 g_bsum + 8192, g_Cst + 131072, g_Hst[2][p ^ 1], g_Xfc);

        // fc: wait for the 8 h2 chunks (1024 cols / 128), then compute
        if (tid < 8) poll_ge(g_ck + ((2 * 16 + tid) << 5), 16u * (unsigned)(t + 1));
        __syncthreads();
        {
            int br = bc >> 4, cg = bc & 15;
            int o = tid >> 3, part = tid & 7;
            int b = br * 8 + (o >> 3);
            int dl = o & 7;
            int d = cg * 8 + dl;
            const float4* hp = (const float4*)(g_Xfc + b * 1024) + part * 16;
            const float4* wp = (const float4*)(sWfc + dl * 1024) + part * 16;
            float acc = 0.f;
#pragma unroll
            for (int k = 0; k < 16; ++k) {
                float4 hv = __ldcg(hp + k);
                float4 wv = wp[k];
                const __half2* h2 = (const __half2*)&hv;
                const __half2* w2 = (const __half2*)&wv;
#pragma unroll
                for (int j = 0; j < 4; ++j) {
                    float2 hf = __half22float2(h2[j]);
                    float2 wf = __half22float2(w2[j]);
                    acc = fmaf(hf.x, wf.x, acc);
                    acc = fmaf(hf.y, wf.y, acc);
                }
            }
            acc += __shfl_xor_sync(0xffffffff, acc, 1);
            acc += __shfl_xor_sync(0xffffffff, acc, 2);
            acc += __shfl_xor_sync(0xffffffff, acc, 4);
            if (part == 0) {
                float z = sigf(acc + bfc[d]);
                float v = (t + 1 < PLEN) ? x[(size_t)(t + 1) * 8192 + b * 128 + d] : z;
                out[(size_t)(t + 1) * 8192 + b * 128 + d] = v;
                g_In0[b * 128 + d] = __float2half(v);
            }
        }
        __threadfence();
        __syncthreads();
        if (tid == 0) release_add(&g_fin);     // In0(t+1) published by this CTA
    }
}

// ---------------- launch (lstm_main is launch #4 for ncu) ----------------
extern "C" void kernel_launch(void* const* d_in, const int* in_sizes, int n_in,
                              void* d_out, int out_size) {
    const float* x    = (const float*)d_in[0];
    const float* h0   = (const float*)d_in[1];
    const float* c0   = (const float*)d_in[2];
    const float* Wih0 = (const float*)d_in[3];
    const float* Whh0 = (const float*)d_in[4];
    const float* bih0 = (const float*)d_in[5];
    const float* bhh0 = (const float*)d_in[6];
    const float* Wih1 = (const float*)d_in[7];
    const float* Whh1 = (const float*)d_in[8];
    const float* bih1 = (const float*)d_in[9];
    const float* bhh1 = (const float*)d_in[10];
    const float* Wih2 = (const float*)d_in[11];
    const float* Whh2 = (const float*)d_in[12];
    const float* bih2 = (const float*)d_in[13];
    const float* bhh2 = (const float*)d_in[14];
    const float* Wfc  = (const float*)d_in[15];
    const float* bfc  = (const float*)d_in[16];
    float* out = (float*)d_out;

    static bool attr_done = false;
    if (!attr_done) {
        cudaFuncSetAttribute(lstm_main, cudaFuncAttributeMaxDynamicSharedMemorySize,
                             SMEM_BYTES);
        attr_done = true;
    }

    int total = L0SZ + 2 * L12SZ;
    pack_all<<<(total + 255) / 256, 256>>>(Wih0, Whh0, Wih1, Whh1, Wih2, Whh2);
    pack_fc<<<512, 256>>>(Wfc);
    init_state<<<768, 256>>>(x, h0, c0, bih0, bhh0, bih1, bhh1, bih2, bhh2, out);
    lstm_main<<<NBLK, NTHR, SMEM_BYTES>>>(x, bfc, out);
}

// round 16
// speedup vs baseline: 1.0977x; 1.0977x over previous
#include <cuda_runtime.h>
#include <cuda_fp16.h>

#define NBLK 256
#define NTHR 256
#define T_STEPS 512
#define PLEN 64

#define BK 128                // k-halves per stage
#define RING 4
#define LA 3
#define SA 136                // smem row stride in halves (BK + 8)
#define ASTAGE (32 * SA)      // halves (A: 32 batch rows x 128 k)
#define BSTAGE (32 * SA)      // halves (B: 32 gate cols x 128 k)
#define NKS 4                 // k-split warps
#define GATES_OFF (RING * (ASTAGE + BSTAGE))            // halves
#define WFC_OFF   (GATES_OFF + NKS * 32 * 33 * 2)       // gates: 4 bufs of 32x33 floats
#define SMEM_BYTES ((WFC_OFF + 1024) * 2)

#define S0 9                  // layer0: 8 H-stages + 1 X-stage (K=1152)
#define S12 16                // layers 1/2: 8 H + 8 X (K=2048)
#define L0SZ (128 * S0 * 4096)
#define L12SZ (128 * S12 * 4096)

// ---------------- device state ----------------
__device__ __half g_Wp0[L0SZ];
__device__ __half g_Wp1[L12SZ];
__device__ __half g_Wp2[L12SZ];
__device__ __half g_Wfch[128 * 1024];
__device__ float  g_bsum[3 * 4096];
__device__ __half g_In0[64 * 128];
__device__ __half g_X1[64 * 1024];
__device__ __half g_X2[64 * 1024];
__device__ __half g_Xfc[64 * 1024];
__device__ __half g_Hst[3][2][64 * 1024];
__device__ float  g_Cst[3 * 64 * 1024];
__device__ unsigned g_count;
__device__ unsigned g_gen;

// ---------------- helpers ----------------
__device__ __forceinline__ float sigf(float v) { return 1.0f / (1.0f + expf(-v)); }

__device__ __forceinline__ unsigned smaddr(const void* p) {
    return (unsigned)__cvta_generic_to_shared(p);
}
__device__ __forceinline__ void cp16(unsigned dst, const void* src) {
    asm volatile("cp.async.cg.shared.global [%0], [%1], 16;" :: "r"(dst), "l"(src));
}
__device__ __forceinline__ void cp_commit() { asm volatile("cp.async.commit_group;"); }

__device__ __forceinline__ void ldsm4(unsigned& r0, unsigned& r1, unsigned& r2, unsigned& r3,
                                      unsigned addr) {
    asm volatile("ldmatrix.sync.aligned.m8n8.x4.shared.b16 {%0,%1,%2,%3}, [%4];"
                 : "=r"(r0), "=r"(r1), "=r"(r2), "=r"(r3) : "r"(addr));
}
__device__ __forceinline__ void mma16816(float c[4],
    unsigned a0, unsigned a1, unsigned a2, unsigned a3, unsigned b0, unsigned b1) {
    asm volatile("mma.sync.aligned.m16n8k16.row.col.f32.f16.f16.f32 "
        "{%0,%1,%2,%3}, {%4,%5,%6,%7}, {%8,%9}, {%0,%1,%2,%3};"
        : "+f"(c[0]), "+f"(c[1]), "+f"(c[2]), "+f"(c[3])
        : "r"(a0), "r"(a1), "r"(a2), "r"(a3), "r"(b0), "r"(b1));
}

// grid barrier: all arrive, all wait (deadlock-safe)
__device__ __forceinline__ void grid_sync() {
    __syncthreads();
    if (threadIdx.x == 0) {
        unsigned gen;
        asm volatile("ld.volatile.global.u32 %0, [%1];" : "=r"(gen) : "l"(&g_gen));
        unsigned arr;
        asm volatile("atom.release.gpu.global.add.u32 %0, [%1], %2;"
                     : "=r"(arr) : "l"(&g_count), "r"(1u));
        if (arr == NBLK - 1) {
            *(volatile unsigned*)&g_count = 0;
            asm volatile("red.release.gpu.global.add.u32 [%0], %1;" :: "l"(&g_gen), "r"(1u));
        } else {
            unsigned cur;
            do {
                asm volatile("ld.acquire.gpu.global.u32 %0, [%1];" : "=r"(cur) : "l"(&g_gen));
            } while (cur == gen);
        }
    }
    __syncthreads();
}

// ---------------- packing / init ----------------
// Wp[((cg*S + s)*32 + col)*128 + kk]; col = gate*8 + nl; H-part first
// (s<8 -> Whh k=s*128+kk; s>=8 -> Wih); row = gate*1024 + cg*8 + nl.
__global__ void pack_all(const float* __restrict__ Wih0, const float* __restrict__ Whh0,
                         const float* __restrict__ Wih1, const float* __restrict__ Whh1,
                         const float* __restrict__ Wih2, const float* __restrict__ Whh2) {
    int idx = blockIdx.x * blockDim.x + threadIdx.x;
    const float *Wih, *Whh;
    __half* Wp;
    int S, Kin, i = idx;
    if (i < L0SZ)               { Wp = g_Wp0; S = S0;  Kin = 128;  Wih = Wih0; Whh = Whh0; }
    else if (i < L0SZ + L12SZ)  { i -= L0SZ;  Wp = g_Wp1; S = S12; Kin = 1024; Wih = Wih1; Whh = Whh1; }
    else if (i < L0SZ + 2*L12SZ){ i -= L0SZ + L12SZ; Wp = g_Wp2; S = S12; Kin = 1024; Wih = Wih2; Whh = Whh2; }
    else return;
    int kk   = i & 127;
    int col  = (i >> 7) & 31;
    int rest = i >> 12;
    int s    = rest % S;
    int cg   = rest / S;
    int row  = ((col >> 3) << 10) + cg * 8 + (col & 7);
    float v  = (s < 8) ? Whh[row * 1024 + s * 128 + kk]
                       : Wih[row * Kin + (s - 8) * 128 + kk];
    Wp[i] = __float2half(v);
}

__global__ void pack_fc(const float* __restrict__ Wfc) {
    int i = blockIdx.x * blockDim.x + threadIdx.x;
    if (i < 128 * 1024) g_Wfch[i] = __float2half(Wfc[i]);
}

__global__ void init_state(const float* __restrict__ x, const float* __restrict__ h0,
                           const float* __restrict__ c0,
                           const float* __restrict__ bih0, const float* __restrict__ bhh0,
                           const float* __restrict__ bih1, const float* __restrict__ bhh1,
                           const float* __restrict__ bih2, const float* __restrict__ bhh2,
                           float* __restrict__ out) {
    int i = blockIdx.x * blockDim.x + threadIdx.x;
    if (i == 0) { g_gen = 0; g_count = 0; }
    if (i < 8192) { float v = x[i]; g_In0[i] = __float2half(v); out[i] = v; }
    if (i < 3 * 65536) {
        g_Hst[i >> 16][0][i & 65535] = __float2half(h0[i]);
        g_Cst[i] = c0[i];
    }
    if (i < 4096) {
        g_bsum[i]        = bih0[i] + bhh0[i];
        g_bsum[4096 + i] = bih1[i] + bhh1[i];
        g_bsum[8192 + i] = bih2[i] + bhh2[i];
    }
}

// ---------------- main persistent kernel ----------------
extern __shared__ __half sm_raw[];

struct Ctx {
    int tid, cg, bh;
    unsigned AsBase, BsBase;
    unsigned aOff, bOff;       // per-lane ldmatrix offsets (bytes)
    int rt, ks;                // warp mapping: 16-row tile, k-chunk (32 halves)
};

__device__ __forceinline__ void load_stage(const Ctx& cx,
    const __half* __restrict__ Hp, const __half* __restrict__ Xin, int ldX,
    const __half* __restrict__ wseg, int s, int slot)
{
    unsigned adst = cx.AsBase + (unsigned)(slot * ASTAGE) * 2u;
    unsigned bdst = cx.BsBase + (unsigned)(slot * BSTAGE) * 2u;
    const __half* a; int ld;
    if (s < 8) { a = Hp + s * BK; ld = 1024; }
    else       { a = Xin + (s - 8) * BK; ld = ldX; }
    a += cx.bh * 32 * ld;                       // this CTA's 32 batch rows
#pragma unroll
    for (int i = 0; i < 2; ++i) {
        int q = cx.tid + i * 256;
        int r = q >> 4, u = q & 15;
        cp16(adst + (unsigned)(r * SA + u * 8) * 2u, a + r * ld + u * 8);
    }
    const __half* w = wseg + (size_t)s * 4096;
#pragma unroll
    for (int i = 0; i < 2; ++i) {
        int q = cx.tid + i * 256;
        int r = q >> 4, u = q & 15;
        cp16(bdst + (unsigned)(r * SA + u * 8) * 2u, w + r * 128 + u * 8);
    }
}

__device__ __forceinline__ void gemm_epi(const Ctx& cx, int stages,
    const __half* __restrict__ Hp, const __half* __restrict__ Xin, int ldX,
    const __half* __restrict__ wseg,
    const float* __restrict__ bsumL, float* __restrict__ Cl,
    __half* __restrict__ Hnext, __half* __restrict__ Xnext)
{
    float* gates = (float*)(sm_raw + GATES_OFF);    // 4 bufs of 32x33 floats

    float acc[2][2][4];
#pragma unroll
    for (int a = 0; a < 2; ++a)
#pragma unroll
        for (int b = 0; b < 2; ++b)
#pragma unroll
            for (int d = 0; d < 4; ++d) acc[a][b][d] = 0.f;

    // prologue: first LA stages are H-part (ready since last step)
#pragma unroll
    for (int s = 0; s < LA; ++s) {
        load_stage(cx, Hp, Xin, ldX, wseg, s, s);
        cp_commit();
    }

#pragma unroll 1
    for (int s = 0; s < stages; ++s) {
        asm volatile("cp.async.wait_group %0;" :: "n"(LA - 1));
        __syncthreads();
        int u = s + LA;
        if (u < stages) load_stage(cx, Hp, Xin, ldX, wseg, u, u & (RING - 1));
        cp_commit();

        int slot = s & (RING - 1);
        unsigned aBase = cx.AsBase + (unsigned)(slot * ASTAGE) * 2u + cx.aOff;
        unsigned bBase = cx.BsBase + (unsigned)(slot * BSTAGE) * 2u + cx.bOff;
#pragma unroll
        for (int kk = 0; kk < 2; ++kk) {
            unsigned b0[4], b1[4];
            ldsm4(b0[0], b0[1], b0[2], b0[3], bBase + kk * 32u);
            ldsm4(b1[0], b1[1], b1[2], b1[3], bBase + 16u * SA * 2u + kk * 32u);
            unsigned a0, a1, a2, a3;
            ldsm4(a0, a1, a2, a3, aBase + kk * 32u);
            mma16816(acc[0][0], a0, a1, a2, a3, b0[0], b0[1]);
            mma16816(acc[0][1], a0, a1, a2, a3, b0[2], b0[3]);
            mma16816(acc[1][0], a0, a1, a2, a3, b1[0], b1[1]);
            mma16816(acc[1][1], a0, a1, a2, a3, b1[2], b1[3]);
        }
    }

    // store partial gates (per k-split buffer): warp tile 16 rows x 32 cols
    {
        const int lane = cx.tid & 31;
        float* gk = gates + cx.ks * (32 * 33);
        int r = lane >> 2, p2 = (lane & 3) * 2;
        int row = cx.rt * 16 + r;
#pragma unroll
        for (int hb = 0; hb < 2; ++hb)
#pragma unroll
            for (int n8 = 0; n8 < 2; ++n8) {
                int col = hb * 16 + n8 * 8 + p2;
                float* q = acc[hb][n8];
                gk[row * 33 + col]           = q[0];
                gk[row * 33 + col + 1]       = q[1];
                gk[(row + 8) * 33 + col]     = q[2];
                gk[(row + 8) * 33 + col + 1] = q[3];
            }
    }
    __syncthreads();

    // fused LSTM cell: 256 threads, one (local batch, hid) each
    {
        int b = cx.tid >> 3, nl = cx.tid & 7;     // b = 0..31 local
        int gb = cx.bh * 32 + b;
        int ng = cx.cg * 8 + nl;
        int e = b * 33 + nl;
        float gi = 0.f, gf = 0.f, gg = 0.f, go = 0.f;
#pragma unroll
        for (int k = 0; k < NKS; ++k) {
            const float* g = gates + k * (32 * 33);
            gi += g[e];
            gf += g[e + 8];
            gg += g[e + 16];
            go += g[e + 24];
        }
        gi += bsumL[ng]; gf += bsumL[1024 + ng];
        gg += bsumL[2048 + ng]; go += bsumL[3072 + ng];
        float c  = Cl[gb * 1024 + ng];
        float cn = sigf(gf) * c + sigf(gi) * tanhf(gg);
        float h  = sigf(go) * tanhf(cn);
        Cl[gb * 1024 + ng] = cn;
        __half hh = __float2half(h);
        Hnext[gb * 1024 + ng] = hh;
        Xnext[gb * 1024 + ng] = hh;
    }
    __syncthreads();
}

__global__ void __launch_bounds__(NTHR, 2)
lstm_main(const float* __restrict__ x, const float* __restrict__ bfc,
          float* __restrict__ out)
{
    const int tid = threadIdx.x, bc = blockIdx.x;
    Ctx cx;
    cx.tid = tid;
    cx.cg = bc >> 1;                   // column group 0..127 (8 hidden units)
    cx.bh = bc & 1;                    // batch half
    cx.AsBase = smaddr(sm_raw);
    cx.BsBase = smaddr(sm_raw + RING * ASTAGE);
    {
        const int lane = tid & 31, wid = tid >> 5;
        cx.rt = wid & 1;               // 16-row tile within 32 rows
        cx.ks = wid >> 1;              // k-chunk 0..3 (32 halves each)
        int aRow = cx.rt * 16 + ((lane >> 3) & 1) * 8 + (lane & 7);
        cx.aOff = (unsigned)(aRow * SA + (lane >> 4) * 8 + cx.ks * 32) * 2u;
        int bRow = ((lane >> 4) & 1) * 8 + (lane & 7);
        cx.bOff = (unsigned)(bRow * SA + ((lane >> 3) & 1) * 8 + cx.ks * 32) * 2u;
    }
    __half* sWfc = sm_raw + WFC_OFF;

    // cache fc weight row d = cg (1024 halves)
    {
        const __half* src = g_Wfch + cx.cg * 1024;
        if (tid < 128) cp16(smaddr(sWfc + tid * 8), src + tid * 8);
        cp_commit();
        asm volatile("cp.async.wait_group 0;");
        __syncthreads();
    }

    const __half* Wb0 = g_Wp0 + (size_t)cx.cg * S0 * 4096;
    const __half* Wb1 = g_Wp1 + (size_t)cx.cg * S12 * 4096;
    const __half* Wb2 = g_Wp2 + (size_t)cx.cg * S12 * 4096;

#pragma unroll 1
    for (int t = 0; t < T_STEPS - 1; ++t) {
        int p = t & 1;

        gemm_epi(cx, S0, g_Hst[0][p], g_In0, 128, Wb0,
                 g_bsum, g_Cst, g_Hst[0][p ^ 1], g_X1);
        grid_sync();
        gemm_epi(cx, S12, g_Hst[1][p], g_X1, 1024, Wb1,
                 g_bsum + 4096, g_Cst + 65536, g_Hst[1][p ^ 1], g_X2);
        grid_sync();
        gemm_epi(cx, S12, g_Hst[2][p], g_X2, 1024, Wb2,
                 g_bsum + 8192, g_Cst + 131072, g_Hst[2][p ^ 1], g_Xfc);
        grid_sync();

        // fc: CTA computes output column d=cg for its 32 batch rows
        {
            int b = cx.bh * 32 + (tid >> 3);
            int part = tid & 7;
            const float4* hp = (const float4*)(g_Xfc + b * 1024) + part * 16;
            const float4* wp = (const float4*)sWfc + part * 16;
            float acc = 0.f;
#pragma unroll
            for (int k = 0; k < 16; ++k) {
                float4 hv = __ldcg(hp + k);
                float4 wv = wp[k];
                const __half2* h2 = (const __half2*)&hv;
                const __half2* w2 = (const __half2*)&wv;
#pragma unroll
                for (int j = 0; j < 4; ++j) {
                    float2 hf = __half22float2(h2[j]);
                    float2 wf = __half22float2(w2[j]);
                    acc = fmaf(hf.x, wf.x, acc);
                    acc = fmaf(hf.y, wf.y, acc);
                }
            }
            acc += __shfl_xor_sync(0xffffffff, acc, 1);
            acc += __shfl_xor_sync(0xffffffff, acc, 2);
            acc += __shfl_xor_sync(0xffffffff, acc, 4);
            if (part == 0) {
                int d = cx.cg;
                float z = sigf(acc + bfc[d]);
                float v = (t + 1 < PLEN) ? x[(size_t)(t + 1) * 8192 + b * 128 + d] : z;
                out[(size_t)(t + 1) * 8192 + b * 128 + d] = v;
                g_In0[b * 128 + d] = __float2half(v);
            }
        }
        grid_sync();
    }
}

// ---------------- launch (lstm_main is launch #4 for ncu) ----------------
extern "C" void kernel_launch(void* const* d_in, const int* in_sizes, int n_in,
                              void* d_out, int out_size) {
    const float* x    = (const float*)d_in[0];
    const float* h0   = (const float*)d_in[1];
    const float* c0   = (const float*)d_in[2];
    const float* Wih0 = (const float*)d_in[3];
    const float* Whh0 = (const float*)d_in[4];
    const float* bih0 = (const float*)d_in[5];
    const float* bhh0 = (const float*)d_in[6];
    const float* Wih1 = (const float*)d_in[7];
    const float* Whh1 = (const float*)d_in[8];
    const float* bih1 = (const float*)d_in[9];
    const float* bhh1 = (const float*)d_in[10];
    const float* Wih2 = (const float*)d_in[11];
    const float* Whh2 = (const float*)d_in[12];
    const float* bih2 = (const float*)d_in[13];
    const float* bhh2 = (const float*)d_in[14];
    const float* Wfc  = (const float*)d_in[15];
    const float* bfc  = (const float*)d_in[16];
    float* out = (float*)d_out;

    static bool attr_done = false;
    if (!attr_done) {
        cudaFuncSetAttribute(lstm_main, cudaFuncAttributeMaxDynamicSharedMemorySize,
                             SMEM_BYTES);
        attr_done = true;
    }

    int total = L0SZ + 2 * L12SZ;
    pack_all<<<(total + 255) / 256, 256>>>(Wih0, Whh0, Wih1, Whh1, Wih2, Whh2);
    pack_fc<<<512, 256>>>(Wfc);
    init_state<<<768, 256>>>(x, h0, c0, bih0, bhh0, bih1, bhh1, bih2, bhh2, out);
    lstm_main<<<NBLK, NTHR, SMEM_BYTES>>>(x, bfc, out);
}